// round 5
// baseline (speedup 1.0000x reference)
#include <cuda_runtime.h>
#include <math.h>
#include <stdint.h>

// Problem constants
#define BB 2
#define SS 2048
#define HH 1024
#define NH 16
#define DD 64

// Scratch: split-head Q/K/V [B, NH, S, D] and pre-Wo attention output [B*S, H]
__device__ float g_Q[(size_t)BB * NH * SS * DD];
__device__ float g_K[(size_t)BB * NH * SS * DD];
__device__ float g_V[(size_t)BB * NH * SS * DD];
__device__ float g_A[(size_t)BB * SS * HH];

// ---------------------------------------------------------------------------
// tf32 helpers
// ---------------------------------------------------------------------------
__device__ __forceinline__ uint32_t f2tf32(float x) {
    uint32_t r;
    asm("cvt.rna.tf32.f32 %0, %1;" : "=r"(r) : "f"(x));
    return r;
}

__device__ __forceinline__ void mma_tf32(float* d, const uint32_t* a, const uint32_t* b) {
    asm volatile(
        "mma.sync.aligned.m16n8k8.row.col.f32.tf32.tf32.f32 "
        "{%0,%1,%2,%3}, {%4,%5,%6,%7}, {%8,%9}, {%0,%1,%2,%3};"
        : "+f"(d[0]), "+f"(d[1]), "+f"(d[2]), "+f"(d[3])
        : "r"(a[0]), "r"(a[1]), "r"(a[2]), "r"(a[3]), "r"(b[0]), "r"(b[1]));
}

// ---------------------------------------------------------------------------
// Fused conv1d('SAME', TAPS) + bias + scale as a tf32 tensor-core GEMM core.
// BM=128, BN=128, BK=16. 256 threads = 8 warps (2m x 4n), warp tile 64x32.
// Double-buffered smem, register-staged global loads, 1 sync / k-iteration.
// A smem uses XOR swizzle col = row ^ (((k>>2)&3)<<3): conflict-free STS
// AND conflict-free fragment LDS (stride 136 => bank = 8k + col mod 32).
// Accumulation order identical to round-3 kernel (bit-identical results).
// ---------------------------------------------------------------------------
template <int TAPS, bool HEADS_OUT>
__device__ __forceinline__ void conv_gemm_core(
    const float* __restrict__ X, const float* __restrict__ W,
    const float* __restrict__ bias, float* __restrict__ Y, float scale,
    int m0, int n0)
{
    __shared__ uint32_t As[2][16][136];   // [buf][k][m^sigma], tf32 bits
    __shared__ uint32_t Bs[2][16][136];   // [buf][k][n], tf32 bits

    const int tid = threadIdx.x;
    const int wid = tid >> 5;
    const int lane = tid & 31;
    const int g = lane >> 2;
    const int tg = lane & 3;
    const int warp_m = wid >> 2;
    const int warp_n = wid & 3;

    // Fixed per-thread staging coordinates
    int arow[2], ac4[2], at[2], ab[2], asw[2];
    int bkk[2], bc4[2];
#pragma unroll
    for (int p = 0; p < 2; ++p) {
        int f = tid + p * 256;
        arow[p] = f >> 2;
        ac4[p] = (f & 3) << 2;
        asw[p] = arow[p] ^ (((ac4[p] >> 2) & 3) << 3);   // swizzled column
        int m = m0 + arow[p];
        ab[p] = m >> 11;
        at[p] = m & (SS - 1);
        bkk[p] = f >> 5;
        bc4[p] = (f & 31) << 2;
    }

    float acc[4][4][4];
#pragma unroll
    for (int i = 0; i < 4; ++i)
#pragma unroll
        for (int j = 0; j < 4; ++j)
#pragma unroll
            for (int r = 0; r < 4; ++r) acc[i][j][r] = 0.f;

    const int CENTER = (TAPS - 1) / 2;
    const int NIT = TAPS * 64;

    float4 va[2], vb[2];

    auto issue_loads = [&](int it) {
        int tap = it >> 6;            // HH/16 == 64
        int c0 = (it & 63) << 4;
        const float* Wt = W + (size_t)tap * HH * HH;
#pragma unroll
        for (int p = 0; p < 2; ++p) {
            int srow = at[p] + tap - CENTER;
            va[p] = make_float4(0.f, 0.f, 0.f, 0.f);
            if (srow >= 0 && srow < SS)
                va[p] = *(const float4*)(X + ((size_t)ab[p] * SS + srow) * HH + c0 + ac4[p]);
            vb[p] = *(const float4*)(Wt + (size_t)(c0 + bkk[p]) * HH + n0 + bc4[p]);
        }
    };
    auto store_tiles = [&](int buf) {
#pragma unroll
        for (int p = 0; p < 2; ++p) {
            As[buf][ac4[p] + 0][asw[p]] = f2tf32(va[p].x);
            As[buf][ac4[p] + 1][asw[p]] = f2tf32(va[p].y);
            As[buf][ac4[p] + 2][asw[p]] = f2tf32(va[p].z);
            As[buf][ac4[p] + 3][asw[p]] = f2tf32(va[p].w);
            uint4 u;
            u.x = f2tf32(vb[p].x); u.y = f2tf32(vb[p].y);
            u.z = f2tf32(vb[p].z); u.w = f2tf32(vb[p].w);
            *(uint4*)&Bs[buf][bkk[p]][bc4[p]] = u;
        }
    };

    // Prologue
    issue_loads(0);
    store_tiles(0);
    __syncthreads();

    for (int it = 0; it < NIT; ++it) {
        const int buf = it & 1;
        if (it + 1 < NIT) issue_loads(it + 1);

#pragma unroll
        for (int ks = 0; ks < 2; ++ks) {
            const int kb = ks * 8;
            const int k1 = kb + tg;
            const int k2 = kb + tg + 4;
            const int s1 = ((k1 >> 2) & 3) << 3;
            const int s2 = ((k2 >> 2) & 3) << 3;
            uint32_t a[4][4];
            uint32_t b[4][2];
#pragma unroll
            for (int mt = 0; mt < 4; ++mt) {
                int mr = warp_m * 64 + mt * 16 + g;
                a[mt][0] = As[buf][k1][mr ^ s1];
                a[mt][1] = As[buf][k1][(mr + 8) ^ s1];
                a[mt][2] = As[buf][k2][mr ^ s2];
                a[mt][3] = As[buf][k2][(mr + 8) ^ s2];
            }
#pragma unroll
            for (int nt = 0; nt < 4; ++nt) {
                int nc = warp_n * 32 + nt * 8 + g;
                b[nt][0] = Bs[buf][k1][nc];
                b[nt][1] = Bs[buf][k2][nc];
            }
#pragma unroll
            for (int mt = 0; mt < 4; ++mt)
#pragma unroll
                for (int nt = 0; nt < 4; ++nt)
                    mma_tf32(acc[mt][nt], a[mt], b[nt]);
        }

        if (it + 1 < NIT) {
            store_tiles(buf ^ 1);
            __syncthreads();
        }
    }

    // Epilogue: bias, scale, layout
#pragma unroll
    for (int mt = 0; mt < 4; ++mt) {
#pragma unroll
        for (int half = 0; half < 2; ++half) {
            int m = m0 + warp_m * 64 + mt * 16 + g + half * 8;
            int bidx = m >> 11;
            int t = m & (SS - 1);
#pragma unroll
            for (int nt = 0; nt < 4; ++nt) {
                int n = n0 + warp_n * 32 + nt * 8 + tg * 2;
                float2 o;
                o.x = (acc[mt][nt][half * 2 + 0] + bias[n + 0]) * scale;
                o.y = (acc[mt][nt][half * 2 + 1] + bias[n + 1]) * scale;
                if (HEADS_OUT) {
                    int h = n >> 6;
                    int d = n & 63;
                    *(float2*)(Y + (((size_t)bidx * NH + h) * SS + t) * DD + d) = o;
                } else {
                    *(float2*)(Y + (size_t)m * HH + n) = o;
                }
            }
        }
    }
}

// Merged Q/K/V conv launch: grid.z selects the projection.
struct Conv3Args {
    const float* X0;            // query_input (z==0)
    const float* X1;            // source_input (z==1,2)
    const float* W[3];
    const float* b[3];
    float* Y[3];
    float scale[3];
};

__global__ __launch_bounds__(256, 2) void conv3_kernel(Conv3Args a)
{
    const int z = blockIdx.z;
    const float* X = (z == 0) ? a.X0 : a.X1;
    conv_gemm_core<3, true>(X, a.W[z], a.b[z], a.Y[z], a.scale[z],
                            blockIdx.y * 128, blockIdx.x * 128);
}

__global__ __launch_bounds__(256, 2) void outproj_kernel(
    const float* __restrict__ X, const float* __restrict__ W,
    const float* __restrict__ bias, float* __restrict__ Y)
{
    conv_gemm_core<1, false>(X, W, bias, Y, 1.0f,
                             blockIdx.y * 128, blockIdx.x * 128);
}

// ---------------------------------------------------------------------------
// Tensor-core flash attention (tf32 m16n8k8) — unchanged from round 3.
// ---------------------------------------------------------------------------
__global__ __launch_bounds__(256) void attn_tc(const float* __restrict__ mask,
                                               float* __restrict__ Aout)
{
    __shared__ uint32_t Kn[64][76];  // K tile, natural [key][d], tf32 bits
    __shared__ uint32_t Vs[64][72];  // V tile, natural [key][d], tf32 bits
    __shared__ float msk[SS];        // mask row * -1e9

    const int q0 = blockIdx.x * 128;
    const int h = blockIdx.y;
    const int b = blockIdx.z;
    const int tid = threadIdx.x;
    const int wid = tid >> 5;
    const int lane = tid & 31;
    const int g = lane >> 2;
    const int tg = lane & 3;
    const size_t base = ((size_t)b * NH + h) * SS * DD;
    const int qr = q0 + wid * 16;

    for (int i = tid; i < SS; i += 256)
        msk[i] = mask[(size_t)b * SS + i] * (-1e9f);

    uint32_t qa[8][4];
    {
        const float* Qp = g_Q + base + (size_t)(qr + g) * DD + tg;
#pragma unroll
        for (int ks = 0; ks < 8; ++ks) {
            qa[ks][0] = f2tf32(Qp[ks * 8]);
            qa[ks][1] = f2tf32(Qp[ks * 8 + 8 * DD]);
            qa[ks][2] = f2tf32(Qp[ks * 8 + 4]);
            qa[ks][3] = f2tf32(Qp[ks * 8 + 4 + 8 * DD]);
        }
    }

    float oacc[8][4];
#pragma unroll
    for (int nt = 0; nt < 8; ++nt)
#pragma unroll
        for (int r = 0; r < 4; ++r) oacc[nt][r] = 0.f;
    float m0 = -1e30f, m8 = -1e30f, l0 = 0.f, l8 = 0.f;

    for (int k0 = 0; k0 < SS; k0 += 64) {
        __syncthreads();
#pragma unroll
        for (int p = 0; p < 4; ++p) {
            int f = tid + p * 256;
            int r = f >> 4;
            int c4 = (f & 15) << 2;
            float4 kv = *(const float4*)(g_K + base + (size_t)(k0 + r) * DD + c4);
            float4 vv = *(const float4*)(g_V + base + (size_t)(k0 + r) * DD + c4);
            uint4 uk, uv;
            uk.x = f2tf32(kv.x); uk.y = f2tf32(kv.y);
            uk.z = f2tf32(kv.z); uk.w = f2tf32(kv.w);
            uv.x = f2tf32(vv.x); uv.y = f2tf32(vv.y);
            uv.z = f2tf32(vv.z); uv.w = f2tf32(vv.w);
            *(uint4*)&Kn[r][c4] = uk;
            *(uint4*)&Vs[r][c4] = uv;
        }
        __syncthreads();

        float sacc[8][4];
#pragma unroll
        for (int nt = 0; nt < 8; ++nt)
#pragma unroll
            for (int r = 0; r < 4; ++r) sacc[nt][r] = 0.f;
#pragma unroll
        for (int ks = 0; ks < 8; ++ks) {
#pragma unroll
            for (int nt = 0; nt < 8; ++nt) {
                uint32_t bfr[2];
                bfr[0] = Kn[nt * 8 + g][ks * 8 + tg];
                bfr[1] = Kn[nt * 8 + g][ks * 8 + tg + 4];
                mma_tf32(sacc[nt], qa[ks], bfr);
            }
        }

#pragma unroll
        for (int nt = 0; nt < 8; ++nt) {
            float mk0 = msk[k0 + nt * 8 + 2 * tg];
            float mk1 = msk[k0 + nt * 8 + 2 * tg + 1];
            sacc[nt][0] += mk0; sacc[nt][1] += mk1;
            sacc[nt][2] += mk0; sacc[nt][3] += mk1;
        }

        float r0 = -1e30f, r8 = -1e30f;
#pragma unroll
        for (int nt = 0; nt < 8; ++nt) {
            r0 = fmaxf(r0, fmaxf(sacc[nt][0], sacc[nt][1]));
            r8 = fmaxf(r8, fmaxf(sacc[nt][2], sacc[nt][3]));
        }
        r0 = fmaxf(r0, __shfl_xor_sync(0xffffffffu, r0, 1));
        r0 = fmaxf(r0, __shfl_xor_sync(0xffffffffu, r0, 2));
        r8 = fmaxf(r8, __shfl_xor_sync(0xffffffffu, r8, 1));
        r8 = fmaxf(r8, __shfl_xor_sync(0xffffffffu, r8, 2));

        float nm0 = fmaxf(m0, r0), nm8 = fmaxf(m8, r8);
        float cr0 = __expf(m0 - nm0), cr8 = __expf(m8 - nm8);

        float s0 = 0.f, s8 = 0.f;
#pragma unroll
        for (int nt = 0; nt < 8; ++nt) {
            sacc[nt][0] = __expf(sacc[nt][0] - nm0);
            sacc[nt][1] = __expf(sacc[nt][1] - nm0);
            sacc[nt][2] = __expf(sacc[nt][2] - nm8);
            sacc[nt][3] = __expf(sacc[nt][3] - nm8);
            s0 += sacc[nt][0] + sacc[nt][1];
            s8 += sacc[nt][2] + sacc[nt][3];
        }
        s0 += __shfl_xor_sync(0xffffffffu, s0, 1);
        s0 += __shfl_xor_sync(0xffffffffu, s0, 2);
        s8 += __shfl_xor_sync(0xffffffffu, s8, 1);
        s8 += __shfl_xor_sync(0xffffffffu, s8, 2);

        l0 = l0 * cr0 + s0;
        l8 = l8 * cr8 + s8;
        m0 = nm0; m8 = nm8;

#pragma unroll
        for (int nt = 0; nt < 8; ++nt) {
            oacc[nt][0] *= cr0; oacc[nt][1] *= cr0;
            oacc[nt][2] *= cr8; oacc[nt][3] *= cr8;
        }

        const int src0 = (g << 2) + (tg >> 1);
        const int src2 = src0 + 2;
        const bool odd = tg & 1;
#pragma unroll
        for (int ks = 0; ks < 8; ++ks) {
            float e00 = __shfl_sync(0xffffffffu, sacc[ks][0], src0);
            float e01 = __shfl_sync(0xffffffffu, sacc[ks][1], src0);
            float e10 = __shfl_sync(0xffffffffu, sacc[ks][2], src0);
            float e11 = __shfl_sync(0xffffffffu, sacc[ks][3], src0);
            float e20 = __shfl_sync(0xffffffffu, sacc[ks][0], src2);
            float e21 = __shfl_sync(0xffffffffu, sacc[ks][1], src2);
            float e30 = __shfl_sync(0xffffffffu, sacc[ks][2], src2);
            float e31 = __shfl_sync(0xffffffffu, sacc[ks][3], src2);
            uint32_t pa[4];
            pa[0] = f2tf32(odd ? e01 : e00);
            pa[1] = f2tf32(odd ? e11 : e10);
            pa[2] = f2tf32(odd ? e21 : e20);
            pa[3] = f2tf32(odd ? e31 : e30);
#pragma unroll
            for (int nt = 0; nt < 8; ++nt) {
                uint32_t bfr[2];
                bfr[0] = Vs[ks * 8 + tg][nt * 8 + g];
                bfr[1] = Vs[ks * 8 + tg + 4][nt * 8 + g];
                mma_tf32(oacc[nt], pa, bfr);
            }
        }
    }

    const float inv0 = 1.f / l0, inv8 = 1.f / l8;
#pragma unroll
    for (int nt = 0; nt < 8; ++nt) {
        float2 o0, o8;
        o0.x = oacc[nt][0] * inv0; o0.y = oacc[nt][1] * inv0;
        o8.x = oacc[nt][2] * inv8; o8.y = oacc[nt][3] * inv8;
        size_t col = (size_t)h * DD + nt * 8 + 2 * tg;
        *(float2*)(Aout + ((size_t)b * SS + qr + g) * HH + col) = o0;
        *(float2*)(Aout + ((size_t)b * SS + qr + g + 8) * HH + col) = o8;
    }
}

// ---------------------------------------------------------------------------
extern "C" void kernel_launch(void* const* d_in, const int* in_sizes, int n_in,
                              void* d_out, int out_size)
{
    const float* qin  = (const float*)d_in[0];
    const float* src  = (const float*)d_in[1];
    const float* mask = (const float*)d_in[2];
    const float* Wq   = (const float*)d_in[3];
    const float* bq   = (const float*)d_in[4];
    const float* Wk   = (const float*)d_in[5];
    const float* bk   = (const float*)d_in[6];
    const float* Wv   = (const float*)d_in[7];
    const float* bv   = (const float*)d_in[8];
    const float* Wo   = (const float*)d_in[9];
    const float* bo   = (const float*)d_in[10];
    float* out = (float*)d_out;

    float *gQ, *gK, *gV, *gA;
    cudaGetSymbolAddress((void**)&gQ, g_Q);
    cudaGetSymbolAddress((void**)&gK, g_K);
    cudaGetSymbolAddress((void**)&gV, g_V);
    cudaGetSymbolAddress((void**)&gA, g_A);

    Conv3Args a;
    a.X0 = qin; a.X1 = src;
    a.W[0] = Wq; a.W[1] = Wk; a.W[2] = Wv;
    a.b[0] = bq; a.b[1] = bk; a.b[2] = bv;
    a.Y[0] = gQ; a.Y[1] = gK; a.Y[2] = gV;
    a.scale[0] = 0.125f; a.scale[1] = 1.0f; a.scale[2] = 1.0f;

    dim3 gridConv3(HH / 128, (BB * SS) / 128, 3);  // (8, 32, 3)
    conv3_kernel<<<gridConv3, 256>>>(a);

    dim3 gridAttn(SS / 128, NH, BB);  // (16, 16, 2)
    attn_tc<<<gridAttn, 256>>>(mask, gA);

    dim3 gridProj(HH / 128, (BB * SS) / 128);  // (8, 32)
    outproj_kernel<<<gridProj, 256>>>(gA, Wo, bo, out);
}

// round 7
// speedup vs baseline: 1.1833x; 1.1833x over previous
#include <cuda_runtime.h>
#include <math.h>
#include <stdint.h>

#define BB 2
#define SS 2048
#define HH 1024
#define NH 16
#define DD 64

// Scratch
__device__ float g_Q[(size_t)BB * NH * SS * DD];
__device__ float g_K[(size_t)BB * NH * SS * DD];
__device__ float g_V[(size_t)BB * NH * SS * DD];
__device__ float g_A[(size_t)BB * SS * HH];
// tf32-bit operands
__device__ uint32_t g_Xqc[(size_t)BB * SS * HH];
__device__ uint32_t g_Xsc[(size_t)BB * SS * HH];
__device__ uint32_t g_Ac[(size_t)BB * SS * HH];
__device__ uint32_t g_Wc[(size_t)10 * HH * HH];  // Wq(3) Wk(3) Wv(3) Wo(1), [k][n]

// ---------------------------------------------------------------------------
__device__ __forceinline__ uint32_t f2tf32(float x) {
    uint32_t r;
    asm("cvt.rna.tf32.f32 %0, %1;" : "=r"(r) : "f"(x));
    return r;
}
__device__ __forceinline__ void mma_tf32(float* d, const uint32_t* a, const uint32_t* b) {
    asm volatile(
        "mma.sync.aligned.m16n8k8.row.col.f32.tf32.tf32.f32 "
        "{%0,%1,%2,%3}, {%4,%5,%6,%7}, {%8,%9}, {%0,%1,%2,%3};"
        : "+f"(d[0]), "+f"(d[1]), "+f"(d[2]), "+f"(d[3])
        : "r"(a[0]), "r"(a[1]), "r"(a[2]), "r"(a[3]), "r"(b[0]), "r"(b[1]));
}
__device__ __forceinline__ uint32_t smem_u32(const void* p) {
    uint32_t a;
    asm("{ .reg .u64 t; cvta.to.shared.u64 t, %1; cvt.u32.u64 %0, t; }" : "=r"(a) : "l"(p));
    return a;
}
#define CP_ASYNC(dst, src, sz) \
    asm volatile("cp.async.cg.shared.global [%0], [%1], 16, %2;" \
                 :: "r"(dst), "l"(src), "r"(sz) : "memory")
#define CP_COMMIT() asm volatile("cp.async.commit_group;" ::: "memory")
#define CP_WAIT2()  asm volatile("cp.async.wait_group 2;" ::: "memory")

// ---------------------------------------------------------------------------
// Pre-conversion kernels (fp32 -> tf32 bits)
// ---------------------------------------------------------------------------
__global__ __launch_bounds__(256) void cvt4(const float* __restrict__ x,
                                            uint32_t* __restrict__ y, int n4)
{
    int i = blockIdx.x * 256 + threadIdx.x;
    if (i < n4) {
        float4 v = ((const float4*)x)[i];
        uint4 u;
        u.x = f2tf32(v.x); u.y = f2tf32(v.y);
        u.z = f2tf32(v.z); u.w = f2tf32(v.w);
        ((uint4*)y)[i] = u;
    }
}
// 10 weight matrices of 1M elements each: z selects
__global__ __launch_bounds__(256) void cvt_w(
    const float* __restrict__ Wq, const float* __restrict__ Wk,
    const float* __restrict__ Wv, const float* __restrict__ Wo,
    uint32_t* __restrict__ y)
{
    int z = blockIdx.z;
    const float* src = z < 3 ? Wq + (size_t)z * HH * HH
                     : z < 6 ? Wk + (size_t)(z - 3) * HH * HH
                     : z < 9 ? Wv + (size_t)(z - 6) * HH * HH
                             : Wo;
    uint32_t* dst = y + (size_t)z * HH * HH;
    int i = blockIdx.x * 256 + threadIdx.x;   // over 1M/4 float4
    float4 v = ((const float4*)src)[i];
    uint4 u;
    u.x = f2tf32(v.x); u.y = f2tf32(v.y);
    u.z = f2tf32(v.z); u.w = f2tf32(v.w);
    ((uint4*)dst)[i] = u;
}

// ---------------------------------------------------------------------------
// cp.async 4-stage tf32 mma GEMM with conv halo.
// BM=BN=128, BK=16, 256 threads = 8 warps (2m x 4n), warp tile 64x32.
// A smem [m][k] stride 20 words (conflict-free: bank = 20g+tg distinct).
// B smem [k][n] stride 128, XOR swizzle n ^ ((k&3)<<3) (conflict-free).
// Accumulation order identical to round-4 kernel: bit-identical results.
// ---------------------------------------------------------------------------
#define A_STRIDE 20
#define STG_WORDS 4608              // A 128*20=2560 + B 16*128=2048
#define STG_BYTES 18432
#define GEMM_DSMEM (4 * STG_BYTES)  // 73728

template <int TAPS, bool HEADS_OUT>
__device__ __forceinline__ void gemm_ca_core(
    const uint32_t* __restrict__ Xc, const uint32_t* __restrict__ Wc,
    const float* __restrict__ bias, float* __restrict__ Y, float scale,
    int m0, int n0)
{
    extern __shared__ uint32_t sm[];
    const uint32_t smb = smem_u32(sm);

    const int tid = threadIdx.x;
    const int wid = tid >> 5;
    const int lane = tid & 31;
    const int g = lane >> 2;
    const int tg = lane & 3;
    const int wm = wid >> 2;
    const int wn = wid & 3;
    const int batch = m0 >> 11;
    const int tb = m0 & (SS - 1);
    const int CENTER = (TAPS - 1) / 2;
    const int NIT = TAPS * 64;

    // staging coords (2 chunks per operand per thread)
    int am[2], ak4[2], bk[2], bn4x[2];
#pragma unroll
    for (int p = 0; p < 2; ++p) {
        int f = tid + p * 256;
        am[p] = f >> 2;
        ak4[p] = (f & 3) << 2;
        bk[p] = f >> 5;
        int n4 = (f & 31) << 2;
        bn4x[p] = bk[p] * 128 + (n4 ^ ((bk[p] & 3) << 3));  // swizzled word idx
    }

    auto issue = [&](int it) {
        const int tap = it >> 6;
        const int c0 = (it & 63) << 4;
        const uint32_t sb = smb + (uint32_t)(it & 3) * STG_BYTES;
        const uint32_t* wt = Wc + (size_t)tap * HH * HH;
#pragma unroll
        for (int p = 0; p < 2; ++p) {
            int srow = tb + am[p] + tap - CENTER;
            uint32_t sz = 16;
            int sr = srow;
            if (TAPS > 1) {
                sz = (srow >= 0 && srow < SS) ? 16u : 0u;
                sr = srow < 0 ? 0 : (srow >= SS ? SS - 1 : srow);
            }
            const uint32_t* srcA = Xc + ((size_t)batch * SS + sr) * HH + c0 + ak4[p];
            CP_ASYNC(sb + (uint32_t)(am[p] * A_STRIDE + ak4[p]) * 4, srcA, sz);
            const uint32_t* srcB = wt + (size_t)(c0 + bk[p]) * HH + n0 + ((bn4x[p] & 127) ^ ((bk[p] & 3) << 3));
            CP_ASYNC(sb + 10240 + (uint32_t)bn4x[p] * 4, srcB, 16u);
        }
    };

    float acc[4][4][4];
#pragma unroll
    for (int i = 0; i < 4; ++i)
#pragma unroll
        for (int j = 0; j < 4; ++j)
#pragma unroll
            for (int r = 0; r < 4; ++r) acc[i][j][r] = 0.f;

    // prologue: 3 stages in flight
#pragma unroll
    for (int s = 0; s < 3; ++s) { issue(s); CP_COMMIT(); }

    for (int it = 0; it < NIT; ++it) {
        CP_WAIT2();
        __syncthreads();

        const uint32_t* sA = sm + (it & 3) * STG_WORDS;
        const uint32_t* sB = sA + 2560;
#pragma unroll
        for (int ks = 0; ks < 2; ++ks) {
            const int k1 = ks * 8 + tg;
            const int k2 = k1 + 4;
            uint32_t a[4][4], b[4][2];
#pragma unroll
            for (int mt = 0; mt < 4; ++mt) {
                int mr = wm * 64 + mt * 16 + g;
                a[mt][0] = sA[mr * A_STRIDE + k1];
                a[mt][1] = sA[(mr + 8) * A_STRIDE + k1];
                a[mt][2] = sA[mr * A_STRIDE + k2];
                a[mt][3] = sA[(mr + 8) * A_STRIDE + k2];
            }
#pragma unroll
            for (int nt = 0; nt < 4; ++nt) {
                int ncx = (wn * 32 + nt * 8 + g) ^ (tg << 3);
                b[nt][0] = sB[k1 * 128 + ncx];
                b[nt][1] = sB[k2 * 128 + ncx];
            }
#pragma unroll
            for (int mt = 0; mt < 4; ++mt)
#pragma unroll
                for (int nt = 0; nt < 4; ++nt)
                    mma_tf32(acc[mt][nt], a[mt], b[nt]);
        }
        __syncthreads();            // all reads of stage (it+3)&3's buffer done
        if (it + 3 < NIT) issue(it + 3);
        CP_COMMIT();                // always commit (possibly empty group)
    }

    // epilogue
#pragma unroll
    for (int mt = 0; mt < 4; ++mt)
#pragma unroll
        for (int half = 0; half < 2; ++half) {
            int m = m0 + wm * 64 + mt * 16 + g + half * 8;
            int bidx = m >> 11;
            int t = m & (SS - 1);
#pragma unroll
            for (int nt = 0; nt < 4; ++nt) {
                int n = n0 + wn * 32 + nt * 8 + tg * 2;
                float2 o;
                o.x = (acc[mt][nt][half * 2 + 0] + bias[n + 0]) * scale;
                o.y = (acc[mt][nt][half * 2 + 1] + bias[n + 1]) * scale;
                if (HEADS_OUT) {
                    int h = n >> 6, d = n & 63;
                    *(float2*)(Y + (((size_t)bidx * NH + h) * SS + t) * DD + d) = o;
                } else {
                    *(float2*)(Y + (size_t)m * HH + n) = o;
                }
            }
        }
}

__global__ __launch_bounds__(256, 2) void conv3_ca(
    const uint32_t* __restrict__ Xq, const uint32_t* __restrict__ Xs,
    const uint32_t* __restrict__ Wc,
    const float* __restrict__ bq, const float* __restrict__ bk,
    const float* __restrict__ bv,
    float* __restrict__ Yq, float* __restrict__ Yk, float* __restrict__ Yv)
{
    const int z = blockIdx.z;
    gemm_ca_core<3, true>(z ? Xs : Xq, Wc + (size_t)z * 3 * HH * HH,
                          z == 0 ? bq : (z == 1 ? bk : bv),
                          z == 0 ? Yq : (z == 1 ? Yk : Yv),
                          z == 0 ? 0.125f : 1.0f,
                          blockIdx.y * 128, blockIdx.x * 128);
}

__global__ __launch_bounds__(256, 2) void outproj_ca(
    const uint32_t* __restrict__ Xc, const uint32_t* __restrict__ Wc,
    const float* __restrict__ bias, float* __restrict__ Y)
{
    gemm_ca_core<1, false>(Xc, Wc + (size_t)9 * HH * HH, bias, Y, 1.0f,
                           blockIdx.y * 128, blockIdx.x * 128);
}

// ---------------------------------------------------------------------------
// Tensor-core flash attention (tf32 m16n8k8) — unchanged (proven).
// ---------------------------------------------------------------------------
__global__ __launch_bounds__(256) void attn_tc(const float* __restrict__ mask,
                                               float* __restrict__ Aout)
{
    __shared__ uint32_t Kn[64][76];
    __shared__ uint32_t Vs[64][72];
    __shared__ float msk[SS];

    const int q0 = blockIdx.x * 128;
    const int h = blockIdx.y;
    const int b = blockIdx.z;
    const int tid = threadIdx.x;
    const int wid = tid >> 5;
    const int lane = tid & 31;
    const int g = lane >> 2;
    const int tg = lane & 3;
    const size_t base = ((size_t)b * NH + h) * SS * DD;
    const int qr = q0 + wid * 16;

    for (int i = tid; i < SS; i += 256)
        msk[i] = mask[(size_t)b * SS + i] * (-1e9f);

    uint32_t qa[8][4];
    {
        const float* Qp = g_Q + base + (size_t)(qr + g) * DD + tg;
#pragma unroll
        for (int ks = 0; ks < 8; ++ks) {
            qa[ks][0] = f2tf32(Qp[ks * 8]);
            qa[ks][1] = f2tf32(Qp[ks * 8 + 8 * DD]);
            qa[ks][2] = f2tf32(Qp[ks * 8 + 4]);
            qa[ks][3] = f2tf32(Qp[ks * 8 + 4 + 8 * DD]);
        }
    }

    float oacc[8][4];
#pragma unroll
    for (int nt = 0; nt < 8; ++nt)
#pragma unroll
        for (int r = 0; r < 4; ++r) oacc[nt][r] = 0.f;
    float m0 = -1e30f, m8 = -1e30f, l0 = 0.f, l8 = 0.f;

    for (int k0 = 0; k0 < SS; k0 += 64) {
        __syncthreads();
#pragma unroll
        for (int p = 0; p < 4; ++p) {
            int f = tid + p * 256;
            int r = f >> 4;
            int c4 = (f & 15) << 2;
            float4 kv = *(const float4*)(g_K + base + (size_t)(k0 + r) * DD + c4);
            float4 vv = *(const float4*)(g_V + base + (size_t)(k0 + r) * DD + c4);
            uint4 uk, uv;
            uk.x = f2tf32(kv.x); uk.y = f2tf32(kv.y);
            uk.z = f2tf32(kv.z); uk.w = f2tf32(kv.w);
            uv.x = f2tf32(vv.x); uv.y = f2tf32(vv.y);
            uv.z = f2tf32(vv.z); uv.w = f2tf32(vv.w);
            *(uint4*)&Kn[r][c4] = uk;
            *(uint4*)&Vs[r][c4] = uv;
        }
        __syncthreads();

        float sacc[8][4];
#pragma unroll
        for (int nt = 0; nt < 8; ++nt)
#pragma unroll
            for (int r = 0; r < 4; ++r) sacc[nt][r] = 0.f;
#pragma unroll
        for (int ks = 0; ks < 8; ++ks)
#pragma unroll
            for (int nt = 0; nt < 8; ++nt) {
                uint32_t bfr[2];
                bfr[0] = Kn[nt * 8 + g][ks * 8 + tg];
                bfr[1] = Kn[nt * 8 + g][ks * 8 + tg + 4];
                mma_tf32(sacc[nt], qa[ks], bfr);
            }

#pragma unroll
        for (int nt = 0; nt < 8; ++nt) {
            float mk0 = msk[k0 + nt * 8 + 2 * tg];
            float mk1 = msk[k0 + nt * 8 + 2 * tg + 1];
            sacc[nt][0] += mk0; sacc[nt][1] += mk1;
            sacc[nt][2] += mk0; sacc[nt][3] += mk1;
        }

        float r0 = -1e30f, r8 = -1e30f;
#pragma unroll
        for (int nt = 0; nt < 8; ++nt) {
            r0 = fmaxf(r0, fmaxf(sacc[nt][0], sacc[nt][1]));
            r8 = fmaxf(r8, fmaxf(sacc[nt][2], sacc[nt][3]));
        }
        r0 = fmaxf(r0, __shfl_xor_sync(0xffffffffu, r0, 1));
        r0 = fmaxf(r0, __shfl_xor_sync(0xffffffffu, r0, 2));
        r8 = fmaxf(r8, __shfl_xor_sync(0xffffffffu, r8, 1));
        r8 = fmaxf(r8, __shfl_xor_sync(0xffffffffu, r8, 2));

        float nm0 = fmaxf(m0, r0), nm8 = fmaxf(m8, r8);
        float cr0 = __expf(m0 - nm0), cr8 = __expf(m8 - nm8);

        float s0 = 0.f, s8 = 0.f;
#pragma unroll
        for (int nt = 0; nt < 8; ++nt) {
            sacc[nt][0] = __expf(sacc[nt][0] - nm0);
            sacc[nt][1] = __expf(sacc[nt][1] - nm0);
            sacc[nt][2] = __expf(sacc[nt][2] - nm8);
            sacc[nt][3] = __expf(sacc[nt][3] - nm8);
            s0 += sacc[nt][0] + sacc[nt][1];
            s8 += sacc[nt][2] + sacc[nt][3];
        }
        s0 += __shfl_xor_sync(0xffffffffu, s0, 1);
        s0 += __shfl_xor_sync(0xffffffffu, s0, 2);
        s8 += __shfl_xor_sync(0xffffffffu, s8, 1);
        s8 += __shfl_xor_sync(0xffffffffu, s8, 2);

        l0 = l0 * cr0 + s0;
        l8 = l8 * cr8 + s8;
        m0 = nm0; m8 = nm8;

#pragma unroll
        for (int nt = 0; nt < 8; ++nt) {
            oacc[nt][0] *= cr0; oacc[nt][1] *= cr0;
            oacc[nt][2] *= cr8; oacc[nt][3] *= cr8;
        }

        const int src0 = (g << 2) + (tg >> 1);
        const int src2 = src0 + 2;
        const bool odd = tg & 1;
#pragma unroll
        for (int ks = 0; ks < 8; ++ks) {
            float e00 = __shfl_sync(0xffffffffu, sacc[ks][0], src0);
            float e01 = __shfl_sync(0xffffffffu, sacc[ks][1], src0);
            float e10 = __shfl_sync(0xffffffffu, sacc[ks][2], src0);
            float e11 = __shfl_sync(0xffffffffu, sacc[ks][3], src0);
            float e20 = __shfl_sync(0xffffffffu, sacc[ks][0], src2);
            float e21 = __shfl_sync(0xffffffffu, sacc[ks][1], src2);
            float e30 = __shfl_sync(0xffffffffu, sacc[ks][2], src2);
            float e31 = __shfl_sync(0xffffffffu, sacc[ks][3], src2);
            uint32_t pa[4];
            pa[0] = f2tf32(odd ? e01 : e00);
            pa[1] = f2tf32(odd ? e11 : e10);
            pa[2] = f2tf32(odd ? e21 : e20);
            pa[3] = f2tf32(odd ? e31 : e30);
#pragma unroll
            for (int nt = 0; nt < 8; ++nt) {
                uint32_t bfr[2];
                bfr[0] = Vs[ks * 8 + tg][nt * 8 + g];
                bfr[1] = Vs[ks * 8 + tg + 4][nt * 8 + g];
                mma_tf32(oacc[nt], pa, bfr);
            }
        }
    }

    const float inv0 = 1.f / l0, inv8 = 1.f / l8;
#pragma unroll
    for (int nt = 0; nt < 8; ++nt) {
        float2 o0, o8;
        o0.x = oacc[nt][0] * inv0; o0.y = oacc[nt][1] * inv0;
        o8.x = oacc[nt][2] * inv8; o8.y = oacc[nt][3] * inv8;
        size_t col = (size_t)h * DD + nt * 8 + 2 * tg;
        *(float2*)(Aout + ((size_t)b * SS + qr + g) * HH + col) = o0;
        *(float2*)(Aout + ((size_t)b * SS + qr + g + 8) * HH + col) = o8;
    }
}

// ---------------------------------------------------------------------------
extern "C" void kernel_launch(void* const* d_in, const int* in_sizes, int n_in,
                              void* d_out, int out_size)
{
    const float* qin  = (const float*)d_in[0];
    const float* src  = (const float*)d_in[1];
    const float* mask = (const float*)d_in[2];
    const float* Wq   = (const float*)d_in[3];
    const float* bq   = (const float*)d_in[4];
    const float* Wk   = (const float*)d_in[5];
    const float* bk   = (const float*)d_in[6];
    const float* Wv   = (const float*)d_in[7];
    const float* bv   = (const float*)d_in[8];
    const float* Wo   = (const float*)d_in[9];
    const float* bo   = (const float*)d_in[10];
    float* out = (float*)d_out;

    float *gQ, *gK, *gV, *gA;
    uint32_t *gXq, *gXs, *gAc, *gW;
    cudaGetSymbolAddress((void**)&gQ, g_Q);
    cudaGetSymbolAddress((void**)&gK, g_K);
    cudaGetSymbolAddress((void**)&gV, g_V);
    cudaGetSymbolAddress((void**)&gA, g_A);
    cudaGetSymbolAddress((void**)&gXq, g_Xqc);
    cudaGetSymbolAddress((void**)&gXs, g_Xsc);
    cudaGetSymbolAddress((void**)&gAc, g_Ac);
    cudaGetSymbolAddress((void**)&gW, g_Wc);

    cudaFuncSetAttribute(conv3_ca, cudaFuncAttributeMaxDynamicSharedMemorySize,
                         GEMM_DSMEM);
    cudaFuncSetAttribute(outproj_ca, cudaFuncAttributeMaxDynamicSharedMemorySize,
                         GEMM_DSMEM);

    const int N4 = BB * SS * HH / 4;             // 1M float4
    cvt4<<<(N4 + 255) / 256, 256>>>(qin, gXq, N4);
    cvt4<<<(N4 + 255) / 256, 256>>>(src, gXs, N4);
    dim3 gridW(HH * HH / 4 / 256, 1, 10);        // (1024, 1, 10)
    cvt_w<<<gridW, 256>>>(Wq, Wk, Wv, Wo, gW);

    dim3 gridC(HH / 128, (BB * SS) / 128, 3);    // (8, 32, 3)
    conv3_ca<<<gridC, 256, GEMM_DSMEM>>>(gXq, gXs, gW, bq, bk, bv, gQ, gK, gV);

    dim3 gridAttn(SS / 128, NH, BB);             // (16, 16, 2)
    attn_tc<<<gridAttn, 256>>>(mask, gA);

    cvt4<<<(N4 + 255) / 256, 256>>>(gA, gAc, N4);
    dim3 gridO(HH / 128, (BB * SS) / 128);       // (8, 32)
    outproj_ca<<<gridO, 256, GEMM_DSMEM>>>(gAc, gW, bo, out);
}